// round 2
// baseline (speedup 1.0000x reference)
#include <cuda_runtime.h>
#include <math_constants.h>

// Problem shape (fixed by the dataset):
//   features [32,256,96]  -> N=8192, D=96
//   predicts [32,256,6625]-> C=6625
//   centers  [6625,96]
#define N_ROWS 8192
#define C_DIM  6625
#define D_DIM  96
#define EPS_V  1e-07f
#define INF_V  1e11f

__device__ float g_row_dist[N_ROWS];

__global__ __launch_bounds__(256)
void center_loss_row_kernel(const float* __restrict__ features,
                            const float* __restrict__ predicts,
                            const float* __restrict__ centers)
{
    const int n   = blockIdx.x;
    const int tid = threadIdx.x;
    const size_t base = (size_t)n * C_DIM;
    const float* __restrict__ row = predicts + base;

    // Row base is only 4B-aligned when n%4 != 0 (6625 % 4 == 1).
    // Scalar prologue up to the next 16B boundary, float4 body, scalar tail.
    const int pre  = (int)((4u - ((unsigned)base & 3u)) & 3u); // 0..3 elems
    const int body = (C_DIM - pre) >> 2;                        // float4 count
    const int vend = pre + (body << 2);                         // first tail elem

    float best = -CUDART_INF_F;
    int   bidx = 0;

    // prologue (<=3 elements)
    if (tid < pre) {
        float v = row[tid];
        if (v > best) { best = v; bidx = tid; }
    }

    // aligned float4 body
    const float4* __restrict__ row4 =
        reinterpret_cast<const float4*>(row + pre);
    for (int i = tid; i < body; i += 256) {
        float4 v = row4[i];
        int b = pre + (i << 2);
        if (v.x > best) { best = v.x; bidx = b;     }
        if (v.y > best) { best = v.y; bidx = b + 1; }
        if (v.z > best) { best = v.z; bidx = b + 2; }
        if (v.w > best) { best = v.w; bidx = b + 3; }
    }

    // tail (<=3 elements)
    for (int i = vend + tid; i < C_DIM; i += 256) {
        float v = row[i];
        if (v > best) { best = v; bidx = i; }
    }

    __shared__ float sv[256];
    __shared__ int   si[256];
    sv[tid] = best;
    si[tid] = bidx;
    __syncthreads();

    // argmax reduction with first-index tie-break (matches jnp.argmax)
    #pragma unroll
    for (int s = 128; s > 0; s >>= 1) {
        if (tid < s) {
            float ov = sv[tid + s];
            int   oi = si[tid + s];
            if (ov > sv[tid] || (ov == sv[tid] && oi < si[tid])) {
                sv[tid] = ov;
                si[tid] = oi;
            }
        }
        __syncthreads();
    }
    const int label = si[0];
    __syncthreads();   // protect sv reuse below

    // ---- dist = sum_d (f[n,d] - c[label,d])^2 ----
    float acc = 0.0f;
    const float* __restrict__ f = features + (size_t)n     * D_DIM;
    const float* __restrict__ c = centers  + (size_t)label * D_DIM;
    for (int d = tid; d < D_DIM; d += 256) {
        float diff = f[d] - c[d];
        acc += diff * diff;
    }
    sv[tid] = acc;
    __syncthreads();
    #pragma unroll
    for (int s = 128; s > 0; s >>= 1) {
        if (tid < s) sv[tid] += sv[tid + s];
        __syncthreads();
    }

    if (tid == 0) {
        float d = sv[0];
        d = fminf(fmaxf(d, EPS_V), INF_V);
        g_row_dist[n] = d;
    }
}

__global__ __launch_bounds__(256)
void center_loss_reduce_kernel(float* __restrict__ out)
{
    const int tid = threadIdx.x;
    double acc = 0.0;
    for (int i = tid; i < N_ROWS; i += 256)
        acc += (double)g_row_dist[i];

    __shared__ double sd[256];
    sd[tid] = acc;
    __syncthreads();
    #pragma unroll
    for (int s = 128; s > 0; s >>= 1) {
        if (tid < s) sd[tid] += sd[tid + s];
        __syncthreads();
    }
    if (tid == 0)
        out[0] = (float)(sd[0] / (double)N_ROWS);
}

extern "C" void kernel_launch(void* const* d_in, const int* in_sizes, int n_in,
                              void* d_out, int out_size)
{
    const float* features = (const float*)d_in[0];
    const float* predicts = (const float*)d_in[1];
    const float* centers  = (const float*)d_in[2];
    float* out = (float*)d_out;

    center_loss_row_kernel<<<N_ROWS, 256>>>(features, predicts, centers);
    center_loss_reduce_kernel<<<1, 256>>>(out);
}

// round 5
// speedup vs baseline: 1.2247x; 1.2247x over previous
#include <cuda_runtime.h>
#include <math_constants.h>

// Problem shape (fixed by the dataset):
//   features [32,256,96]  -> N=8192, D=96
//   predicts [32,256,6625]-> C=6625
//   centers  [6625,96]
#define N_ROWS 8192
#define C_DIM  6625
#define D_DIM  96
#define EPS_V  1e-07f
#define INF_V  1e11f

#define WARPS_PER_CTA 8
#define CTA_THREADS   (WARPS_PER_CTA * 32)
#define GRID_CTAS     (N_ROWS / WARPS_PER_CTA)   // 1024

__device__ float g_row_dist[N_ROWS];
__device__ int   g_done = 0;     // self-resetting completion counter

__global__ __launch_bounds__(CTA_THREADS)
void center_loss_fused_kernel(const float* __restrict__ features,
                              const float* __restrict__ predicts,
                              const float* __restrict__ centers,
                              float* __restrict__ out)
{
    const int tid  = threadIdx.x;
    const int warp = tid >> 5;
    const int lane = tid & 31;
    const int n    = blockIdx.x * WARPS_PER_CTA + warp;   // row handled by this warp

    const size_t base = (size_t)n * C_DIM;
    const float* __restrict__ row = predicts + base;

    // Row base is 16B-aligned only when n%4==0 (6625 % 4 == 1).
    const int pre  = (int)((4u - ((unsigned)base & 3u)) & 3u); // 0..3 scalar elems
    const int body = (C_DIM - pre) >> 2;                       // float4 count
    const int vend = pre + (body << 2);

    float best = -CUDART_INF_F;
    int   bidx = 0;

    if (lane < pre) {
        float v = row[lane];
        if (v > best) { best = v; bidx = lane; }
    }

    const float4* __restrict__ row4 = reinterpret_cast<const float4*>(row + pre);

    // Unrolled x4: 4 independent LDG.128 in flight per lane.
    int i = lane;
    for (; i + 96 < body; i += 128) {
        float4 v0 = row4[i];
        float4 v1 = row4[i + 32];
        float4 v2 = row4[i + 64];
        float4 v3 = row4[i + 96];
        int b0 = pre + (i << 2);
        if (v0.x > best) { best = v0.x; bidx = b0;     }
        if (v0.y > best) { best = v0.y; bidx = b0 + 1; }
        if (v0.z > best) { best = v0.z; bidx = b0 + 2; }
        if (v0.w > best) { best = v0.w; bidx = b0 + 3; }
        int b1 = b0 + 128;
        if (v1.x > best) { best = v1.x; bidx = b1;     }
        if (v1.y > best) { best = v1.y; bidx = b1 + 1; }
        if (v1.z > best) { best = v1.z; bidx = b1 + 2; }
        if (v1.w > best) { best = v1.w; bidx = b1 + 3; }
        int b2 = b0 + 256;
        if (v2.x > best) { best = v2.x; bidx = b2;     }
        if (v2.y > best) { best = v2.y; bidx = b2 + 1; }
        if (v2.z > best) { best = v2.z; bidx = b2 + 2; }
        if (v2.w > best) { best = v2.w; bidx = b2 + 3; }
        int b3 = b0 + 384;
        if (v3.x > best) { best = v3.x; bidx = b3;     }
        if (v3.y > best) { best = v3.y; bidx = b3 + 1; }
        if (v3.z > best) { best = v3.z; bidx = b3 + 2; }
        if (v3.w > best) { best = v3.w; bidx = b3 + 3; }
    }
    for (; i < body; i += 32) {
        float4 v = row4[i];
        int b = pre + (i << 2);
        if (v.x > best) { best = v.x; bidx = b;     }
        if (v.y > best) { best = v.y; bidx = b + 1; }
        if (v.z > best) { best = v.z; bidx = b + 2; }
        if (v.w > best) { best = v.w; bidx = b + 3; }
    }
    for (int t = vend + lane; t < C_DIM; t += 32) {
        float v = row[t];
        if (v > best) { best = v; bidx = t; }
    }

    // Warp argmax reduction, first-index tie-break (matches jnp.argmax).
    #pragma unroll
    for (int s = 16; s > 0; s >>= 1) {
        float ov = __shfl_down_sync(0xFFFFFFFF, best, s);
        int   oi = __shfl_down_sync(0xFFFFFFFF, bidx, s);
        if (ov > best || (ov == best && oi < bidx)) { best = ov; bidx = oi; }
    }
    const int label = __shfl_sync(0xFFFFFFFF, bidx, 0);

    // dist = sum_d (f[n,d] - c[label,d])^2 ; D=96 = 24 float4 per row.
    float acc = 0.0f;
    if (lane < 24) {
        const float4* __restrict__ f4 =
            reinterpret_cast<const float4*>(features + (size_t)n * D_DIM);
        const float4* __restrict__ c4 =
            reinterpret_cast<const float4*>(centers + (size_t)label * D_DIM);
        float4 f = f4[lane];
        float4 c = c4[lane];
        float dx = f.x - c.x, dy = f.y - c.y, dz = f.z - c.z, dw = f.w - c.w;
        acc = dx * dx + dy * dy + dz * dz + dw * dw;
    }
    #pragma unroll
    for (int s = 16; s > 0; s >>= 1)
        acc += __shfl_down_sync(0xFFFFFFFF, acc, s);

    if (lane == 0)
        g_row_dist[n] = fminf(fmaxf(acc, EPS_V), INF_V);

    // ---- last CTA performs the final (deterministic) reduction ----
    __shared__ int s_last;
    __threadfence();
    __syncthreads();
    if (tid == 0) {
        int prev = atomicAdd(&g_done, 1);
        s_last = (prev == GRID_CTAS - 1);
    }
    __syncthreads();

    if (s_last) {
        double a = 0.0;
        for (int k = tid; k < N_ROWS; k += CTA_THREADS)
            a += (double)g_row_dist[k];

        __shared__ double sd[CTA_THREADS];
        sd[tid] = a;
        __syncthreads();
        #pragma unroll
        for (int s = CTA_THREADS / 2; s > 0; s >>= 1) {
            if (tid < s) sd[tid] += sd[tid + s];
            __syncthreads();
        }
        if (tid == 0) {
            out[0] = (float)(sd[0] / (double)N_ROWS);
            g_done = 0;   // reset for next graph replay
        }
    }
}

extern "C" void kernel_launch(void* const* d_in, const int* in_sizes, int n_in,
                              void* d_out, int out_size)
{
    const float* features = (const float*)d_in[0];
    const float* predicts = (const float*)d_in[1];
    const float* centers  = (const float*)d_in[2];
    float* out = (float*)d_out;

    center_loss_fused_kernel<<<GRID_CTAS, CTA_THREADS>>>(features, predicts,
                                                         centers, out);
}